// round 1
// baseline (speedup 1.0000x reference)
#include <cuda_runtime.h>
#include <cstdint>

#define NS 8          // tokens per node
#define DD 128        // model dim
#define NH 4          // heads
#define DH 32         // head dim

#define MAXN 20000
#define MAXM (MAXN * NS)          // 160000 rows
#define MAXE 100000

// -------- device scratch (allocation-free rule: __device__ globals) --------
__device__ float g_dstproj[MAXM * 384];   // [q|k|v] per dst-node token
__device__ float g_srcproj[MAXM * 256];   // [k|v] per src-node token (Wb folded)
__device__ float g_sum[MAXM * DD];        // pre-Wo segment sum
__device__ float g_cnt[MAXN];
__device__ float g_Wf[256 * DD];          // folded [Wk@Wb ; Wv@Wb]
__device__ float g_bf[256];               // folded biases

// ---------------------------------------------------------------------------
__global__ void zero_kernel(float* __restrict__ p, int n) {
    int i = blockIdx.x * blockDim.x + threadIdx.x;
    if (i < n) p[i] = 0.f;
}

// Fold Wb into K/V projections: Wf[o,d] = sum_j Win[128+o, j] * Wb[j, d]
// bf[o] = sum_j Win[128+o, j]*bb[j] + bin[128+o]   (o in [0,256))
__global__ void fold_kernel(const float* __restrict__ Win, const float* __restrict__ Wb,
                            const float* __restrict__ bb, const float* __restrict__ bin,
                            float* __restrict__ Wf, float* __restrict__ bf) {
    int id = blockIdx.x * blockDim.x + threadIdx.x;   // 32768 threads
    int o = id >> 7, d = id & 127;
    const float* wrow = Win + (size_t)(128 + o) * DD;
    float acc = 0.f;
    #pragma unroll 8
    for (int j = 0; j < DD; j++) acc += wrow[j] * Wb[j * DD + d];
    Wf[o * DD + d] = acc;
    if (d == 0) {
        float b = 0.f;
        for (int j = 0; j < DD; j++) b += wrow[j] * bb[j];
        bf[o] = b + bin[128 + o];
    }
}

// ---------------------------------------------------------------------------
// C[M, Nout] = alpha * ( rowscale(A) @ B^T + bpresent*bias ), optionally +=.
// A: [M,128] row-major, B: [Nout,128] row-major (K contiguous in both).
// If cnt != nullptr: rowscale = (cnt[row/8] > 0) ? 1/cnt : 0; bpresent = cnt>0.
// Tiles: 64x64, K-tile 32, 256 threads, 4x4 per thread.
__global__ __launch_bounds__(256)
void gemm128(const float* __restrict__ A, const float* __restrict__ B,
             const float* __restrict__ bias, float* __restrict__ C,
             int ldc, const float* __restrict__ cnt,
             float alpha, int accumulate) {
    __shared__ float As[32][68];   // [k][m], padded
    __shared__ float Bs[32][68];   // [k][n], padded
    const int m0 = blockIdx.y * 64;
    const int n0 = blockIdx.x * 64;
    const int t  = threadIdx.x;
    const int ty = t >> 4, tx = t & 15;

    float acc[4][4] = {};

    for (int k0 = 0; k0 < 128; k0 += 32) {
        #pragma unroll
        for (int r = 0; r < 2; r++) {
            int idx = t + r * 256;            // 0..511
            int row = idx >> 3, kg = idx & 7;
            float4 a4 = *(const float4*)(A + (size_t)(m0 + row) * DD + k0 + kg * 4);
            if (cnt) {
                float c = cnt[(m0 + row) >> 3];
                float rs = (c > 0.f) ? (1.f / c) : 0.f;
                a4.x *= rs; a4.y *= rs; a4.z *= rs; a4.w *= rs;
            }
            As[kg * 4 + 0][row] = a4.x;
            As[kg * 4 + 1][row] = a4.y;
            As[kg * 4 + 2][row] = a4.z;
            As[kg * 4 + 3][row] = a4.w;
            float4 b4 = *(const float4*)(B + (size_t)(n0 + row) * DD + k0 + kg * 4);
            Bs[kg * 4 + 0][row] = b4.x;
            Bs[kg * 4 + 1][row] = b4.y;
            Bs[kg * 4 + 2][row] = b4.z;
            Bs[kg * 4 + 3][row] = b4.w;
        }
        __syncthreads();
        #pragma unroll
        for (int k = 0; k < 32; k++) {
            float4 a = *(float4*)(&As[k][ty * 4]);
            float4 b = *(float4*)(&Bs[k][tx * 4]);
            acc[0][0] += a.x * b.x; acc[0][1] += a.x * b.y; acc[0][2] += a.x * b.z; acc[0][3] += a.x * b.w;
            acc[1][0] += a.y * b.x; acc[1][1] += a.y * b.y; acc[1][2] += a.y * b.z; acc[1][3] += a.y * b.w;
            acc[2][0] += a.z * b.x; acc[2][1] += a.z * b.y; acc[2][2] += a.z * b.z; acc[2][3] += a.z * b.w;
            acc[3][0] += a.w * b.x; acc[3][1] += a.w * b.y; acc[3][2] += a.w * b.z; acc[3][3] += a.w * b.w;
        }
        __syncthreads();
    }

    #pragma unroll
    for (int i = 0; i < 4; i++) {
        int row = m0 + ty * 4 + i;
        float bp = 1.f;
        if (cnt) bp = (cnt[row >> 3] > 0.f) ? 1.f : 0.f;
        #pragma unroll
        for (int j = 0; j < 4; j++) {
            int col = n0 + tx * 4 + j;
            float v = alpha * (acc[i][j] + bp * bias[col]);
            float* cp = C + (size_t)row * ldc + col;
            if (accumulate) *cp += v; else *cp = v;
        }
    }
}

// ---------------------------------------------------------------------------
// One block (128 threads) per edge. Gathers q[8][128], k/v[16][128] from the
// precomputed per-node projections, does 4-head attention, scatters the
// pre-Wo output into g_sum[dst] with vectorized reductions.
__global__ __launch_bounds__(128)
void edge_attn_kernel(const int* __restrict__ ei, int E,
                      const float* __restrict__ dstproj,
                      const float* __restrict__ srcproj,
                      float* __restrict__ gsum,
                      float* __restrict__ gcnt) {
    __shared__ float sq[8][132];     // padded: row stride 132 (4 mod 32 banks)
    __shared__ float sk[16][132];
    __shared__ float sv[16][132];
    __shared__ float satt[32][16];

    const int e = blockIdx.x;
    const int t = threadIdx.x;
    const int src = ei[e];
    const int dst = ei[E + e];

    const float* dp = dstproj + (size_t)dst * (NS * 384);
    const float* sp = srcproj + (size_t)src * (NS * 256);

    // cooperative gather: 256 float4 per tensor slice
    for (int i = t; i < 256; i += 128) {
        int s = i >> 5, c = i & 31;
        *(float4*)(&sq[s][c * 4])     = *(const float4*)(dp + s * 384 + c * 4);
        *(float4*)(&sk[s][c * 4])     = *(const float4*)(dp + s * 384 + 128 + c * 4);
        *(float4*)(&sv[s][c * 4])     = *(const float4*)(dp + s * 384 + 256 + c * 4);
        *(float4*)(&sk[8 + s][c * 4]) = *(const float4*)(sp + s * 256 + c * 4);
        *(float4*)(&sv[8 + s][c * 4]) = *(const float4*)(sp + s * 256 + 128 + c * 4);
    }
    __syncthreads();

    const int p  = t >> 2;     // (head, query) pair 0..31
    const int h  = p >> 3;     // head 0..3
    const int qi = p & 7;      // query token 0..7
    const int g  = t & 3;      // key-group within quad

    const float scale = 0.17677669529663687f;   // 1/sqrt(32)

    float4 qr[8];
    #pragma unroll
    for (int u = 0; u < 8; u++) qr[u] = *(float4*)(&sq[qi][h * DH + u * 4]);

    float logit[4];
    #pragma unroll
    for (int j = 0; j < 4; j++) {
        int kk = g + j * 4;
        float acc = 0.f;
        #pragma unroll
        for (int u = 0; u < 8; u++) {
            float4 kr = *(float4*)(&sk[kk][h * DH + u * 4]);
            acc += qr[u].x * kr.x + qr[u].y * kr.y + qr[u].z * kr.z + qr[u].w * kr.w;
        }
        logit[j] = acc * scale;
    }

    // softmax over 16 keys: local 4 + quad shuffle (lanes 4p..4p+3)
    float m = fmaxf(fmaxf(logit[0], logit[1]), fmaxf(logit[2], logit[3]));
    m = fmaxf(m, __shfl_xor_sync(0xffffffffu, m, 1));
    m = fmaxf(m, __shfl_xor_sync(0xffffffffu, m, 2));
    float pr[4], es = 0.f;
    #pragma unroll
    for (int j = 0; j < 4; j++) { pr[j] = __expf(logit[j] - m); es += pr[j]; }
    es += __shfl_xor_sync(0xffffffffu, es, 1);
    es += __shfl_xor_sync(0xffffffffu, es, 2);
    float inv = 1.f / es;
    #pragma unroll
    for (int j = 0; j < 4; j++) satt[p][g + j * 4] = pr[j] * inv;
    __syncthreads();

    // o[qi][h*32 + g*8 .. +8] = att @ v
    float o[8];
    #pragma unroll
    for (int d = 0; d < 8; d++) o[d] = 0.f;
    #pragma unroll
    for (int kk = 0; kk < 16; kk++) {
        float a = satt[p][kk];
        const float* vr = &sv[kk][h * DH + g * 8];
        #pragma unroll
        for (int d = 0; d < 8; d++) o[d] += a * vr[d];
    }

    float* outp = gsum + (size_t)dst * (NS * DD) + qi * DD + h * DH + g * 8;
    asm volatile("red.global.add.v4.f32 [%0], {%1,%2,%3,%4};" ::
                 "l"(outp), "f"(o[0]), "f"(o[1]), "f"(o[2]), "f"(o[3]) : "memory");
    asm volatile("red.global.add.v4.f32 [%0], {%1,%2,%3,%4};" ::
                 "l"(outp + 4), "f"(o[4]), "f"(o[5]), "f"(o[6]), "f"(o[7]) : "memory");
    if (t == 0) atomicAdd(gcnt + dst, 1.0f);
}

// ---------------------------------------------------------------------------
extern "C" void kernel_launch(void* const* d_in, const int* in_sizes, int n_in,
                              void* d_out, int out_size) {
    const float* x_a = (const float*)d_in[0];
    const float* x_b = (const float*)d_in[1];
    const int* ei[3] = {(const int*)d_in[2], (const int*)d_in[3], (const int*)d_in[4]};
    const int E  = in_sizes[2] / 2;
    const int Nn = in_sizes[0] / (NS * DD);
    const int M  = Nn * NS;

    float *dstproj, *srcproj, *sum, *cnt, *Wf, *bf;
    cudaGetSymbolAddress((void**)&dstproj, g_dstproj);
    cudaGetSymbolAddress((void**)&srcproj, g_srcproj);
    cudaGetSymbolAddress((void**)&sum, g_sum);
    cudaGetSymbolAddress((void**)&cnt, g_cnt);
    cudaGetSymbolAddress((void**)&Wf, g_Wf);
    cudaGetSymbolAddress((void**)&bf, g_bf);

    float* out = (float*)d_out;

    // relation table: r1 (a->b) writes out[1]; r2 (b->a) & r3 (a->a) mean into out[0]
    const float* xsrc[3] = {x_a, x_b, x_a};
    const float* xdst[3] = {x_b, x_a, x_a};
    float* outp[3]  = {out + (size_t)M * DD, out, out};
    float alpha[3]  = {1.f, 0.5f, 0.5f};
    int   accum[3]  = {0, 0, 1};

    for (int r = 0; r < 3; r++) {
        const float* Wb  = (const float*)d_in[5 + r * 6 + 0];
        const float* bb  = (const float*)d_in[5 + r * 6 + 1];
        const float* Win = (const float*)d_in[5 + r * 6 + 2];
        const float* bin = (const float*)d_in[5 + r * 6 + 3];
        const float* Wo  = (const float*)d_in[5 + r * 6 + 4];
        const float* bo  = (const float*)d_in[5 + r * 6 + 5];

        fold_kernel<<<128, 256>>>(Win, Wb, bb, bin, Wf, bf);
        zero_kernel<<<(M * DD + 255) / 256, 256>>>(sum, M * DD);
        zero_kernel<<<(Nn + 255) / 256, 256>>>(cnt, Nn);

        // per-node projections (dst: q|k|v ; src: folded k|v)
        gemm128<<<dim3(6, M / 64), 256>>>(xdst[r], Win, bin, dstproj, 384, nullptr, 1.f, 0);
        gemm128<<<dim3(4, M / 64), 256>>>(xsrc[r], Wf, bf, srcproj, 256, nullptr, 1.f, 0);

        // per-edge attention + scatter
        edge_attn_kernel<<<E, 128>>>(ei[r], E, dstproj, srcproj, sum, cnt);

        // mean + Wo + bias (+combine across relations)
        gemm128<<<dim3(2, M / 64), 256>>>(sum, Wo, bo, outp[r], DD, cnt, alpha[r], accum[r]);
    }
}

// round 2
// speedup vs baseline: 1.5901x; 1.5901x over previous
#include <cuda_runtime.h>
#include <cstdint>

#define NS 8          // tokens per node
#define DD 128        // model dim
#define NH 4          // heads
#define DH 32         // head dim

#define MAXN 20000
#define MAXM (MAXN * NS)          // 160000 rows
#define MAXE 100000

// -------- device scratch (allocation-free rule: __device__ globals) --------
__device__ float g_dstproj[MAXM * 384];   // [q|k|v] per dst-node token
__device__ float g_srcproj[MAXM * 256];   // [k|v] per src-node token (Wb folded)
__device__ float g_sum[MAXM * DD];        // pre-Wo segment sum
__device__ float g_cnt[MAXN];
__device__ float g_Wf[256 * DD];          // folded [Wk@Wb ; Wv@Wb]
__device__ float g_bf[256];               // folded biases

// ---------------------------------------------------------------------------
__global__ void zero_kernel(float* __restrict__ p, int n) {
    int i = blockIdx.x * blockDim.x + threadIdx.x;
    if (i < n) p[i] = 0.f;
}

// Fold Wb into K/V projections: Wf[o,d] = sum_j Win[128+o, j] * Wb[j, d]
// bf[o] = sum_j Win[128+o, j]*bb[j] + bin[128+o]   (o in [0,256))
__global__ void fold_kernel(const float* __restrict__ Win, const float* __restrict__ Wb,
                            const float* __restrict__ bb, const float* __restrict__ bin,
                            float* __restrict__ Wf, float* __restrict__ bf) {
    int id = blockIdx.x * blockDim.x + threadIdx.x;   // 32768 threads
    int o = id >> 7, d = id & 127;
    const float* wrow = Win + (size_t)(128 + o) * DD;
    float acc = 0.f;
    #pragma unroll 8
    for (int j = 0; j < DD; j++) acc += wrow[j] * Wb[j * DD + d];
    Wf[o * DD + d] = acc;
    if (d == 0) {
        float b = 0.f;
        for (int j = 0; j < DD; j++) b += wrow[j] * bb[j];
        bf[o] = b + bin[128 + o];
    }
}

// ---------------------------------------------------------------------------
__device__ __forceinline__ uint32_t f2tf32(float x) {
    uint32_t r;
    asm("cvt.rna.tf32.f32 %0, %1;" : "=r"(r) : "f"(x));
    return r;
}

// C[M, Nout] = alpha * ( rowscale(A) @ B^T + bpresent*bias ), optionally +=.
// A: [M,128] row-major, B: [Nout,128] row-major (K contiguous in both).
// If cnt != nullptr: rowscale = (cnt[row/8] > 0) ? 1/cnt : 0; bpresent = cnt>0.
// tf32 tensor cores: 128x64 block tile, 8 warps each 32x32 (2x4 m16n8k8 tiles).
__global__ __launch_bounds__(256)
void gemm_tf32(const float* __restrict__ A, const float* __restrict__ B,
               const float* __restrict__ bias, float* __restrict__ C,
               int ldc, const float* __restrict__ cnt,
               float alpha, int accumulate) {
    // stride 36: bank = (36*row + col)%32 = (4*row + col)%32 -> conflict-free frags
    __shared__ uint32_t As[128][36];
    __shared__ uint32_t Bs[64][36];

    const int t    = threadIdx.x;
    const int lane = t & 31;
    const int warp = t >> 5;
    const int wm   = warp >> 1;          // 0..3 -> 32-row slice
    const int wn   = warp & 1;           // 0..1 -> 32-col slice
    const int m0   = blockIdx.y * 128;
    const int n0   = blockIdx.x * 64;
    const int lg   = lane >> 2;          // groupID 0..7
    const int lt   = lane & 3;           // threadID_in_group 0..3

    float acc[2][4][4] = {};             // [mtile][ntile][c0..c3]

    for (int k0 = 0; k0 < 128; k0 += 32) {
        // ---- fill A tile: 128x32 floats = 1024 float4, 4 per thread ----
        #pragma unroll
        for (int r = 0; r < 4; r++) {
            int idx = t + r * 256;
            int row = idx >> 3, c4 = idx & 7;
            float4 v = *(const float4*)(A + (size_t)(m0 + row) * DD + k0 + c4 * 4);
            if (cnt) {
                float c = cnt[(m0 + row) >> 3];
                float rs = (c > 0.f) ? (1.f / c) : 0.f;
                v.x *= rs; v.y *= rs; v.z *= rs; v.w *= rs;
            }
            As[row][c4 * 4 + 0] = f2tf32(v.x);
            As[row][c4 * 4 + 1] = f2tf32(v.y);
            As[row][c4 * 4 + 2] = f2tf32(v.z);
            As[row][c4 * 4 + 3] = f2tf32(v.w);
        }
        // ---- fill B tile: 64x32 floats = 512 float4, 2 per thread ----
        #pragma unroll
        for (int r = 0; r < 2; r++) {
            int idx = t + r * 256;
            int row = idx >> 3, c4 = idx & 7;
            float4 v = *(const float4*)(B + (size_t)(n0 + row) * DD + k0 + c4 * 4);
            Bs[row][c4 * 4 + 0] = f2tf32(v.x);
            Bs[row][c4 * 4 + 1] = f2tf32(v.y);
            Bs[row][c4 * 4 + 2] = f2tf32(v.z);
            Bs[row][c4 * 4 + 3] = f2tf32(v.w);
        }
        __syncthreads();

        #pragma unroll
        for (int ks = 0; ks < 4; ks++) {
            const int kk = ks * 8;
            uint32_t af[2][4], bf_[4][2];
            #pragma unroll
            for (int mt = 0; mt < 2; mt++) {
                int rbase = wm * 32 + mt * 16;
                af[mt][0] = As[rbase + lg][kk + lt];
                af[mt][1] = As[rbase + 8 + lg][kk + lt];
                af[mt][2] = As[rbase + lg][kk + 4 + lt];
                af[mt][3] = As[rbase + 8 + lg][kk + 4 + lt];
            }
            #pragma unroll
            for (int nt = 0; nt < 4; nt++) {
                int nrow = wn * 32 + nt * 8 + lg;
                bf_[nt][0] = Bs[nrow][kk + lt];
                bf_[nt][1] = Bs[nrow][kk + 4 + lt];
            }
            #pragma unroll
            for (int mt = 0; mt < 2; mt++) {
                #pragma unroll
                for (int nt = 0; nt < 4; nt++) {
                    asm volatile(
                        "mma.sync.aligned.m16n8k8.row.col.f32.tf32.tf32.f32 "
                        "{%0,%1,%2,%3}, {%4,%5,%6,%7}, {%8,%9}, {%0,%1,%2,%3};"
                        : "+f"(acc[mt][nt][0]), "+f"(acc[mt][nt][1]),
                          "+f"(acc[mt][nt][2]), "+f"(acc[mt][nt][3])
                        : "r"(af[mt][0]), "r"(af[mt][1]), "r"(af[mt][2]), "r"(af[mt][3]),
                          "r"(bf_[nt][0]), "r"(bf_[nt][1]));
                }
            }
        }
        __syncthreads();
    }

    // ---- epilogue: bias, cnt-gating, alpha, optional accumulate ----
    #pragma unroll
    for (int mt = 0; mt < 2; mt++) {
        int r0 = m0 + wm * 32 + mt * 16 + lg;
        int r1 = r0 + 8;
        float bp0 = 1.f, bp1 = 1.f;
        if (cnt) {
            bp0 = (cnt[r0 >> 3] > 0.f) ? 1.f : 0.f;
            bp1 = (cnt[r1 >> 3] > 0.f) ? 1.f : 0.f;
        }
        #pragma unroll
        for (int nt = 0; nt < 4; nt++) {
            int col = n0 + wn * 32 + nt * 8 + 2 * lt;
            float b0 = bias[col], b1 = bias[col + 1];
            float v00 = alpha * (acc[mt][nt][0] + bp0 * b0);
            float v01 = alpha * (acc[mt][nt][1] + bp0 * b1);
            float v10 = alpha * (acc[mt][nt][2] + bp1 * b0);
            float v11 = alpha * (acc[mt][nt][3] + bp1 * b1);
            float* p0 = C + (size_t)r0 * ldc + col;
            float* p1 = C + (size_t)r1 * ldc + col;
            if (accumulate) {
                p0[0] += v00; p0[1] += v01;
                p1[0] += v10; p1[1] += v11;
            } else {
                *(float2*)p0 = make_float2(v00, v01);
                *(float2*)p1 = make_float2(v10, v11);
            }
        }
    }
}

// ---------------------------------------------------------------------------
// One block (128 threads) per edge. Gathers q[8][128], k/v[16][128] from the
// precomputed per-node projections, does 4-head attention, scatters the
// pre-Wo output into g_sum[dst] with vectorized reductions.
__global__ __launch_bounds__(128)
void edge_attn_kernel(const int* __restrict__ ei, int E,
                      const float* __restrict__ dstproj,
                      const float* __restrict__ srcproj,
                      float* __restrict__ gsum,
                      float* __restrict__ gcnt) {
    __shared__ float sq[8][132];     // padded: row stride 132 (4 mod 32 banks)
    __shared__ float sk[16][132];
    __shared__ float sv[16][132];
    __shared__ float satt[32][16];

    const int e = blockIdx.x;
    const int t = threadIdx.x;
    const int src = ei[e];
    const int dst = ei[E + e];

    const float* dp = dstproj + (size_t)dst * (NS * 384);
    const float* sp = srcproj + (size_t)src * (NS * 256);

    // cooperative gather: 256 float4 per tensor slice
    for (int i = t; i < 256; i += 128) {
        int s = i >> 5, c = i & 31;
        *(float4*)(&sq[s][c * 4])     = *(const float4*)(dp + s * 384 + c * 4);
        *(float4*)(&sk[s][c * 4])     = *(const float4*)(dp + s * 384 + 128 + c * 4);
        *(float4*)(&sv[s][c * 4])     = *(const float4*)(dp + s * 384 + 256 + c * 4);
        *(float4*)(&sk[8 + s][c * 4]) = *(const float4*)(sp + s * 256 + c * 4);
        *(float4*)(&sv[8 + s][c * 4]) = *(const float4*)(sp + s * 256 + 128 + c * 4);
    }
    __syncthreads();

    const int p  = t >> 2;     // (head, query) pair 0..31
    const int h  = p >> 3;     // head 0..3
    const int qi = p & 7;      // query token 0..7
    const int g  = t & 3;      // key-group within quad

    const float scale = 0.17677669529663687f;   // 1/sqrt(32)

    float4 qr[8];
    #pragma unroll
    for (int u = 0; u < 8; u++) qr[u] = *(float4*)(&sq[qi][h * DH + u * 4]);

    float logit[4];
    #pragma unroll
    for (int j = 0; j < 4; j++) {
        int kk = g + j * 4;
        float acc = 0.f;
        #pragma unroll
        for (int u = 0; u < 8; u++) {
            float4 kr = *(float4*)(&sk[kk][h * DH + u * 4]);
            acc += qr[u].x * kr.x + qr[u].y * kr.y + qr[u].z * kr.z + qr[u].w * kr.w;
        }
        logit[j] = acc * scale;
    }

    // softmax over 16 keys: local 4 + quad shuffle (lanes 4p..4p+3)
    float m = fmaxf(fmaxf(logit[0], logit[1]), fmaxf(logit[2], logit[3]));
    m = fmaxf(m, __shfl_xor_sync(0xffffffffu, m, 1));
    m = fmaxf(m, __shfl_xor_sync(0xffffffffu, m, 2));
    float pr[4], es = 0.f;
    #pragma unroll
    for (int j = 0; j < 4; j++) { pr[j] = __expf(logit[j] - m); es += pr[j]; }
    es += __shfl_xor_sync(0xffffffffu, es, 1);
    es += __shfl_xor_sync(0xffffffffu, es, 2);
    float inv = 1.f / es;
    #pragma unroll
    for (int j = 0; j < 4; j++) satt[p][g + j * 4] = pr[j] * inv;
    __syncthreads();

    // o[qi][h*32 + g*8 .. +8] = att @ v
    float o[8];
    #pragma unroll
    for (int d = 0; d < 8; d++) o[d] = 0.f;
    #pragma unroll
    for (int kk = 0; kk < 16; kk++) {
        float a = satt[p][kk];
        const float* vr = &sv[kk][h * DH + g * 8];
        #pragma unroll
        for (int d = 0; d < 8; d++) o[d] += a * vr[d];
    }

    float* outp = gsum + (size_t)dst * (NS * DD) + qi * DD + h * DH + g * 8;
    asm volatile("red.global.add.v4.f32 [%0], {%1,%2,%3,%4};" ::
                 "l"(outp), "f"(o[0]), "f"(o[1]), "f"(o[2]), "f"(o[3]) : "memory");
    asm volatile("red.global.add.v4.f32 [%0], {%1,%2,%3,%4};" ::
                 "l"(outp + 4), "f"(o[4]), "f"(o[5]), "f"(o[6]), "f"(o[7]) : "memory");
    if (t == 0) atomicAdd(gcnt + dst, 1.0f);
}

// ---------------------------------------------------------------------------
extern "C" void kernel_launch(void* const* d_in, const int* in_sizes, int n_in,
                              void* d_out, int out_size) {
    const float* x_a = (const float*)d_in[0];
    const float* x_b = (const float*)d_in[1];
    const int* ei[3] = {(const int*)d_in[2], (const int*)d_in[3], (const int*)d_in[4]};
    const int E  = in_sizes[2] / 2;
    const int Nn = in_sizes[0] / (NS * DD);
    const int M  = Nn * NS;

    float *dstproj, *srcproj, *sum, *cnt, *Wf, *bf;
    cudaGetSymbolAddress((void**)&dstproj, g_dstproj);
    cudaGetSymbolAddress((void**)&srcproj, g_srcproj);
    cudaGetSymbolAddress((void**)&sum, g_sum);
    cudaGetSymbolAddress((void**)&cnt, g_cnt);
    cudaGetSymbolAddress((void**)&Wf, g_Wf);
    cudaGetSymbolAddress((void**)&bf, g_bf);

    float* out = (float*)d_out;

    // relation table: r1 (a->b) writes out[1]; r2 (b->a) & r3 (a->a) mean into out[0]
    const float* xsrc[3] = {x_a, x_b, x_a};
    const float* xdst[3] = {x_b, x_a, x_a};
    float* outp[3]  = {out + (size_t)M * DD, out, out};
    float alpha[3]  = {1.f, 0.5f, 0.5f};
    int   accum[3]  = {0, 0, 1};

    for (int r = 0; r < 3; r++) {
        const float* Wb  = (const float*)d_in[5 + r * 6 + 0];
        const float* bb  = (const float*)d_in[5 + r * 6 + 1];
        const float* Win = (const float*)d_in[5 + r * 6 + 2];
        const float* bin = (const float*)d_in[5 + r * 6 + 3];
        const float* Wo  = (const float*)d_in[5 + r * 6 + 4];
        const float* bo  = (const float*)d_in[5 + r * 6 + 5];

        fold_kernel<<<128, 256>>>(Win, Wb, bb, bin, Wf, bf);
        zero_kernel<<<(M * DD + 255) / 256, 256>>>(sum, M * DD);
        zero_kernel<<<(Nn + 255) / 256, 256>>>(cnt, Nn);

        // per-node projections (dst: q|k|v ; src: folded k|v)
        gemm_tf32<<<dim3(6, M / 128), 256>>>(xdst[r], Win, bin, dstproj, 384, nullptr, 1.f, 0);
        gemm_tf32<<<dim3(4, M / 128), 256>>>(xsrc[r], Wf, bf, srcproj, 256, nullptr, 1.f, 0);

        // per-edge attention + scatter
        edge_attn_kernel<<<E, 128>>>(ei[r], E, dstproj, srcproj, sum, cnt);

        // mean + Wo + bias (+combine across relations)
        gemm_tf32<<<dim3(2, M / 128), 256>>>(sum, Wo, bo, outp[r], DD, cnt, alpha[r], accum[r]);
    }
}

// round 3
// speedup vs baseline: 2.1297x; 1.3394x over previous
#include <cuda_runtime.h>
#include <cstdint>

#define NS 8          // tokens per node
#define DD 128        // model dim
#define NH 4          // heads
#define DH 32         // head dim

#define MAXN 20000
#define MAXM (MAXN * NS)          // 160000 rows
#define MAXE 100000

// -------- device scratch (allocation-free rule: __device__ globals) --------
__device__ float g_dstproj[MAXM * 384];   // [q|k|v] per dst-node token
__device__ float g_srcproj[MAXM * 256];   // [k|v] per src-node token (Wb folded)
__device__ float g_sum[MAXM * DD];        // pre-Wo segment sum
__device__ float g_cnt[MAXN];
__device__ float g_Wf[256 * DD];          // folded [Wk@Wb ; Wv@Wb]
__device__ float g_bf[256];               // folded biases
__device__ int   g_hist[MAXN];
__device__ int   g_off[MAXN + 1];
__device__ int   g_cur[MAXN];
__device__ int   g_csr[MAXE];             // src node per edge, grouped by dst

// ---------------------------------------------------------------------------
__global__ void zero2_int_kernel(int* __restrict__ a, int* __restrict__ b, int n) {
    int i = blockIdx.x * blockDim.x + threadIdx.x;
    if (i < n) { a[i] = 0; b[i] = 0; }
}

__global__ void hist_kernel(const int* __restrict__ ei, int E, int* __restrict__ hist) {
    int i = blockIdx.x * blockDim.x + threadIdx.x;
    if (i < E) atomicAdd(hist + ei[E + i], 1);
}

__global__ __launch_bounds__(1024)
void scan_kernel(const int* __restrict__ hist, int* __restrict__ off, int N) {
    __shared__ int part[1025];
    const int t = threadIdx.x;
    const int chunk = (N + 1023) >> 10;
    const int lo = t * chunk;
    const int hi = min(lo + chunk, N);
    int s = 0;
    for (int i = lo; i < hi; i++) s += hist[i];
    part[t] = s;
    __syncthreads();
    if (t == 0) {
        int acc = 0;
        for (int i = 0; i < 1024; i++) { int v = part[i]; part[i] = acc; acc += v; }
        part[1024] = acc;
        off[N] = acc;
    }
    __syncthreads();
    int acc = part[t];
    for (int i = lo; i < hi; i++) { off[i] = acc; acc += hist[i]; }
}

__global__ void scatter_kernel(const int* __restrict__ ei, int E,
                               const int* __restrict__ off, int* __restrict__ cur,
                               int* __restrict__ csr) {
    int i = blockIdx.x * blockDim.x + threadIdx.x;
    if (i < E) {
        int dst = ei[E + i];
        int pos = atomicAdd(cur + dst, 1);
        csr[off[dst] + pos] = ei[i];
    }
}

__global__ void cnt_kernel(const int* __restrict__ off, float* __restrict__ cnt, int N) {
    int i = blockIdx.x * blockDim.x + threadIdx.x;
    if (i < N) cnt[i] = (float)(off[i + 1] - off[i]);
}

// Fold Wb into K/V projections: Wf[o,d] = sum_j Win[128+o, j] * Wb[j, d]
__global__ void fold_kernel(const float* __restrict__ Win, const float* __restrict__ Wb,
                            const float* __restrict__ bb, const float* __restrict__ bin,
                            float* __restrict__ Wf, float* __restrict__ bf) {
    int id = blockIdx.x * blockDim.x + threadIdx.x;
    int o = id >> 7, d = id & 127;
    const float* wrow = Win + (size_t)(128 + o) * DD;
    float acc = 0.f;
    #pragma unroll 8
    for (int j = 0; j < DD; j++) acc += wrow[j] * Wb[j * DD + d];
    Wf[o * DD + d] = acc;
    if (d == 0) {
        float b = 0.f;
        for (int j = 0; j < DD; j++) b += wrow[j] * bb[j];
        bf[o] = b + bin[128 + o];
    }
}

// ---------------------------------------------------------------------------
__device__ __forceinline__ uint32_t f2tf32(float x) {
    uint32_t r;
    asm("cvt.rna.tf32.f32 %0, %1;" : "=r"(r) : "f"(x));
    return r;
}

// C[M, Nout] = alpha * ( rowscale(A) @ B^T + bpresent*bias ), optionally +=.
__global__ __launch_bounds__(256)
void gemm_tf32(const float* __restrict__ A, const float* __restrict__ B,
               const float* __restrict__ bias, float* __restrict__ C,
               int ldc, const float* __restrict__ cnt,
               float alpha, int accumulate) {
    __shared__ uint32_t As[128][36];
    __shared__ uint32_t Bs[64][36];

    const int t    = threadIdx.x;
    const int lane = t & 31;
    const int warp = t >> 5;
    const int wm   = warp >> 1;
    const int wn   = warp & 1;
    const int m0   = blockIdx.y * 128;
    const int n0   = blockIdx.x * 64;
    const int lg   = lane >> 2;
    const int lt   = lane & 3;

    float acc[2][4][4] = {};

    for (int k0 = 0; k0 < 128; k0 += 32) {
        #pragma unroll
        for (int r = 0; r < 4; r++) {
            int idx = t + r * 256;
            int row = idx >> 3, c4 = idx & 7;
            float4 v = *(const float4*)(A + (size_t)(m0 + row) * DD + k0 + c4 * 4);
            if (cnt) {
                float c = cnt[(m0 + row) >> 3];
                float rs = (c > 0.f) ? (1.f / c) : 0.f;
                v.x *= rs; v.y *= rs; v.z *= rs; v.w *= rs;
            }
            As[row][c4 * 4 + 0] = f2tf32(v.x);
            As[row][c4 * 4 + 1] = f2tf32(v.y);
            As[row][c4 * 4 + 2] = f2tf32(v.z);
            As[row][c4 * 4 + 3] = f2tf32(v.w);
        }
        #pragma unroll
        for (int r = 0; r < 2; r++) {
            int idx = t + r * 256;
            int row = idx >> 3, c4 = idx & 7;
            float4 v = *(const float4*)(B + (size_t)(n0 + row) * DD + k0 + c4 * 4);
            Bs[row][c4 * 4 + 0] = f2tf32(v.x);
            Bs[row][c4 * 4 + 1] = f2tf32(v.y);
            Bs[row][c4 * 4 + 2] = f2tf32(v.z);
            Bs[row][c4 * 4 + 3] = f2tf32(v.w);
        }
        __syncthreads();

        #pragma unroll
        for (int ks = 0; ks < 4; ks++) {
            const int kk = ks * 8;
            uint32_t af[2][4], bf_[4][2];
            #pragma unroll
            for (int mt = 0; mt < 2; mt++) {
                int rbase = wm * 32 + mt * 16;
                af[mt][0] = As[rbase + lg][kk + lt];
                af[mt][1] = As[rbase + 8 + lg][kk + lt];
                af[mt][2] = As[rbase + lg][kk + 4 + lt];
                af[mt][3] = As[rbase + 8 + lg][kk + 4 + lt];
            }
            #pragma unroll
            for (int nt = 0; nt < 4; nt++) {
                int nrow = wn * 32 + nt * 8 + lg;
                bf_[nt][0] = Bs[nrow][kk + lt];
                bf_[nt][1] = Bs[nrow][kk + 4 + lt];
            }
            #pragma unroll
            for (int mt = 0; mt < 2; mt++) {
                #pragma unroll
                for (int nt = 0; nt < 4; nt++) {
                    asm volatile(
                        "mma.sync.aligned.m16n8k8.row.col.f32.tf32.tf32.f32 "
                        "{%0,%1,%2,%3}, {%4,%5,%6,%7}, {%8,%9}, {%0,%1,%2,%3};"
                        : "+f"(acc[mt][nt][0]), "+f"(acc[mt][nt][1]),
                          "+f"(acc[mt][nt][2]), "+f"(acc[mt][nt][3])
                        : "r"(af[mt][0]), "r"(af[mt][1]), "r"(af[mt][2]), "r"(af[mt][3]),
                          "r"(bf_[nt][0]), "r"(bf_[nt][1]));
                }
            }
        }
        __syncthreads();
    }

    #pragma unroll
    for (int mt = 0; mt < 2; mt++) {
        int r0 = m0 + wm * 32 + mt * 16 + lg;
        int r1 = r0 + 8;
        float bp0 = 1.f, bp1 = 1.f;
        if (cnt) {
            bp0 = (cnt[r0 >> 3] > 0.f) ? 1.f : 0.f;
            bp1 = (cnt[r1 >> 3] > 0.f) ? 1.f : 0.f;
        }
        #pragma unroll
        for (int nt = 0; nt < 4; nt++) {
            int col = n0 + wn * 32 + nt * 8 + 2 * lt;
            float b0 = bias[col], b1 = bias[col + 1];
            float v00 = alpha * (acc[mt][nt][0] + bp0 * b0);
            float v01 = alpha * (acc[mt][nt][1] + bp0 * b1);
            float v10 = alpha * (acc[mt][nt][2] + bp1 * b0);
            float v11 = alpha * (acc[mt][nt][3] + bp1 * b1);
            float* p0 = C + (size_t)r0 * ldc + col;
            float* p1 = C + (size_t)r1 * ldc + col;
            if (accumulate) {
                p0[0] += v00; p0[1] += v01;
                p1[0] += v10; p1[1] += v11;
            } else {
                *(float2*)p0 = make_float2(v00, v01);
                *(float2*)p1 = make_float2(v10, v11);
            }
        }
    }
}

// ---------------------------------------------------------------------------
__device__ __forceinline__ void cp_async16(void* smem, const void* gmem) {
    uint32_t s = (uint32_t)__cvta_generic_to_shared(smem);
    asm volatile("cp.async.cg.shared.global [%0], [%1], 16;" :: "r"(s), "l"(gmem));
}
__device__ __forceinline__ void cp_commit() {
    asm volatile("cp.async.commit_group;");
}
template <int N> __device__ __forceinline__ void cp_wait() {
    asm volatile("cp.async.wait_group %0;" :: "n"(N));
}

// One block per dst node. Loads dst q/k/v once, precomputes dst-key logits,
// then streams this node's edges (src k/v, cp.async double-buffered),
// accumulating the pre-Wo attention output in registers. No atomics.
#define SORT_CAP 128
__global__ __launch_bounds__(128)
void node_attn_kernel(const int* __restrict__ off, const int* __restrict__ csr,
                      const float* __restrict__ dstproj,
                      const float* __restrict__ srcproj,
                      float* __restrict__ gsum) {
    __shared__ float sq[8][132];
    __shared__ float skd[8][132];
    __shared__ float svd[8][132];
    __shared__ float sks[2][8][132];
    __shared__ float svs[2][8][132];
    __shared__ int   elist[SORT_CAP];

    const int n = blockIdx.x;
    const int t = threadIdx.x;
    const int off0 = off[n];
    const int deg  = off[n + 1] - off0;
    if (deg == 0) return;

    // cache + sort edge list (determinism: accumulate in sorted-src order)
    const bool cached = (deg <= SORT_CAP);
    if (cached) {
        for (int i = t; i < deg; i += 128) elist[i] = csr[off0 + i];
        __syncthreads();
        if (t == 0) {
            for (int i = 1; i < deg; i++) {
                int v = elist[i], j = i - 1;
                while (j >= 0 && elist[j] > v) { elist[j + 1] = elist[j]; j--; }
                elist[j + 1] = v;
            }
        }
    }

    // load dst q/k/v: 3*256 float4
    const float* dp = dstproj + (size_t)n * (NS * 384);
    for (int i = t; i < 256; i += 128) {
        int s = i >> 5, c = i & 31;
        *(float4*)(&sq[s][c * 4])  = *(const float4*)(dp + s * 384 + c * 4);
        *(float4*)(&skd[s][c * 4]) = *(const float4*)(dp + s * 384 + 128 + c * 4);
        *(float4*)(&svd[s][c * 4]) = *(const float4*)(dp + s * 384 + 256 + c * 4);
    }
    __syncthreads();

    const int p  = t >> 2;     // (head, query) pair 0..31
    const int h  = p >> 3;
    const int qi = p & 7;
    const int g  = t & 3;
    const float scale = 0.17677669529663687f;   // 1/sqrt(32)

    float4 qr[8];
    #pragma unroll
    for (int u = 0; u < 8; u++) qr[u] = *(float4*)(&sq[qi][h * DH + u * 4]);

    // precompute dst-key logits (keys g and g+4), scaled
    float ldl[2];
    #pragma unroll
    for (int j = 0; j < 2; j++) {
        int kk = g + j * 4;
        float acc = 0.f;
        #pragma unroll
        for (int u = 0; u < 8; u++) {
            float4 kr = *(float4*)(&skd[kk][h * DH + u * 4]);
            acc += qr[u].x * kr.x + qr[u].y * kr.y + qr[u].z * kr.z + qr[u].w * kr.w;
        }
        ldl[j] = acc * scale;
    }

    float o[8];
    #pragma unroll
    for (int d = 0; d < 8; d++) o[d] = 0.f;

    // prologue: stage edge 0 src k/v
    {
        int s0 = cached ? elist[0] : csr[off0];
        const float* sp = srcproj + (size_t)s0 * (NS * 256);
        #pragma unroll
        for (int r = 0; r < 2; r++) {
            int i = t + r * 128;
            int s = i >> 5, c = i & 31;
            cp_async16(&sks[0][s][c * 4], sp + s * 256 + c * 4);
            cp_async16(&svs[0][s][c * 4], sp + s * 256 + 128 + c * 4);
        }
        cp_commit();
    }

    for (int e = 0; e < deg; e++) {
        const int b = e & 1;
        if (e + 1 < deg) {
            int sn = cached ? elist[e + 1] : csr[off0 + e + 1];
            const float* sp = srcproj + (size_t)sn * (NS * 256);
            #pragma unroll
            for (int r = 0; r < 2; r++) {
                int i = t + r * 128;
                int s = i >> 5, c = i & 31;
                cp_async16(&sks[b ^ 1][s][c * 4], sp + s * 256 + c * 4);
                cp_async16(&svs[b ^ 1][s][c * 4], sp + s * 256 + 128 + c * 4);
            }
            cp_commit();
            cp_wait<1>();
        } else {
            cp_wait<0>();
        }
        __syncthreads();

        // src-key logits (keys 8+g, 12+g)
        float l[4];
        l[0] = ldl[0]; l[1] = ldl[1];
        #pragma unroll
        for (int j = 0; j < 2; j++) {
            int kk = g + j * 4;
            float acc = 0.f;
            #pragma unroll
            for (int u = 0; u < 8; u++) {
                float4 kr = *(float4*)(&sks[b][kk][h * DH + u * 4]);
                acc += qr[u].x * kr.x + qr[u].y * kr.y + qr[u].z * kr.z + qr[u].w * kr.w;
            }
            l[2 + j] = acc * scale;
        }

        // softmax over 16 keys (4 local + quad shuffle)
        float m = fmaxf(fmaxf(l[0], l[1]), fmaxf(l[2], l[3]));
        m = fmaxf(m, __shfl_xor_sync(0xffffffffu, m, 1));
        m = fmaxf(m, __shfl_xor_sync(0xffffffffu, m, 2));
        float pr[4], es = 0.f;
        #pragma unroll
        for (int j = 0; j < 4; j++) { pr[j] = __expf(l[j] - m); es += pr[j]; }
        es += __shfl_xor_sync(0xffffffffu, es, 1);
        es += __shfl_xor_sync(0xffffffffu, es, 2);
        float inv = 1.f / es;
        float att[4];
        #pragma unroll
        for (int j = 0; j < 4; j++) att[j] = pr[j] * inv;

        // o += att @ [v_dst ; v_src]  (att for key kk lives in quad lane kk&3, slot kk>>2)
        const int lbase = (t & 31) & ~3;
        #pragma unroll
        for (int kk = 0; kk < 16; kk++) {
            float a = __shfl_sync(0xffffffffu, att[kk >> 2], lbase | (kk & 3));
            const float* vr = (kk < 8) ? &svd[kk][h * DH + g * 8]
                                       : &svs[b][kk - 8][h * DH + g * 8];
            #pragma unroll
            for (int d = 0; d < 8; d++) o[d] += a * vr[d];
        }
        __syncthreads();
    }

    float* outp = gsum + (size_t)n * (NS * DD) + qi * DD + h * DH + g * 8;
    *(float4*)outp       = make_float4(o[0], o[1], o[2], o[3]);
    *(float4*)(outp + 4) = make_float4(o[4], o[5], o[6], o[7]);
}

// ---------------------------------------------------------------------------
extern "C" void kernel_launch(void* const* d_in, const int* in_sizes, int n_in,
                              void* d_out, int out_size) {
    const float* x_a = (const float*)d_in[0];
    const float* x_b = (const float*)d_in[1];
    const int* ei[3] = {(const int*)d_in[2], (const int*)d_in[3], (const int*)d_in[4]};
    const int E  = in_sizes[2] / 2;
    const int Nn = in_sizes[0] / (NS * DD);
    const int M  = Nn * NS;

    float *dstproj, *srcproj, *sum, *cnt, *Wf, *bf;
    int *hist, *off, *cur, *csr;
    cudaGetSymbolAddress((void**)&dstproj, g_dstproj);
    cudaGetSymbolAddress((void**)&srcproj, g_srcproj);
    cudaGetSymbolAddress((void**)&sum, g_sum);
    cudaGetSymbolAddress((void**)&cnt, g_cnt);
    cudaGetSymbolAddress((void**)&Wf, g_Wf);
    cudaGetSymbolAddress((void**)&bf, g_bf);
    cudaGetSymbolAddress((void**)&hist, g_hist);
    cudaGetSymbolAddress((void**)&off, g_off);
    cudaGetSymbolAddress((void**)&cur, g_cur);
    cudaGetSymbolAddress((void**)&csr, g_csr);

    float* out = (float*)d_out;

    const float* xsrc[3] = {x_a, x_b, x_a};
    const float* xdst[3] = {x_b, x_a, x_a};
    float* outp[3]  = {out + (size_t)M * DD, out, out};
    float alpha[3]  = {1.f, 0.5f, 0.5f};
    int   accum[3]  = {0, 0, 1};

    for (int r = 0; r < 3; r++) {
        const float* Wb  = (const float*)d_in[5 + r * 6 + 0];
        const float* bb  = (const float*)d_in[5 + r * 6 + 1];
        const float* Win = (const float*)d_in[5 + r * 6 + 2];
        const float* bin = (const float*)d_in[5 + r * 6 + 3];
        const float* Wo  = (const float*)d_in[5 + r * 6 + 4];
        const float* bo  = (const float*)d_in[5 + r * 6 + 5];

        // ---- CSR build (by dst) ----
        zero2_int_kernel<<<(Nn + 255) / 256, 256>>>(hist, cur, Nn);
        hist_kernel<<<(E + 255) / 256, 256>>>(ei[r], E, hist);
        scan_kernel<<<1, 1024>>>(hist, off, Nn);
        scatter_kernel<<<(E + 255) / 256, 256>>>(ei[r], E, off, cur, csr);
        cnt_kernel<<<(Nn + 255) / 256, 256>>>(off, cnt, Nn);

        fold_kernel<<<128, 256>>>(Win, Wb, bb, bin, Wf, bf);

        // per-node projections (dst: q|k|v ; src: folded k|v)
        gemm_tf32<<<dim3(6, M / 128), 256>>>(xdst[r], Win, bin, dstproj, 384, nullptr, 1.f, 0);
        gemm_tf32<<<dim3(4, M / 128), 256>>>(xsrc[r], Wf, bf, srcproj, 256, nullptr, 1.f, 0);

        // grouped per-node attention + direct segment sum (no atomics)
        node_attn_kernel<<<Nn, 128>>>(off, csr, dstproj, srcproj, sum);

        // mean + Wo + bias (+combine across relations)
        gemm_tf32<<<dim3(2, M / 128), 256>>>(sum, Wo, bo, outp[r], DD, cnt, alpha[r], accum[r]);
    }
}